// round 14
// baseline (speedup 1.0000x reference)
#include <cuda_runtime.h>
#include <cstdint>

typedef uint32_t u32;

#define IN_DIM 16
#define HID 32
#define OUT_DIM 8
#define TPB 128
#define TILE_M 128   /* 4 warps x 32 rows (mt=2) */

/* ---- fragment-ordered tf32 weight tables ----
   uint4 = {b(j=0), b(j=1), b(j=2), b(j=3)} per lane; pairs consumed as (x,y)|(z,w).
   k-perm: pair u, slot j in 0..3  ->  logical k = 16u + 4*ctg + j
   n-perm (32-col groups): slot (nt4, g) -> n = (nt4>>1)*16 + (nt4&1)*2 + (g>>1)*4 + (g&1) */
__device__ uint4 gB1[768];   /* z: nt 0..3 | r: nt 4..7, 3 pairs x 32 lanes */
__device__ uint4 gBh[384];   /* h~ : 3 pairs x 4 nt x 32 lanes */
__device__ uint4 gBl[64];    /* lin: 2 pairs x 1 nt x 32 lanes */

/* ---------------- helpers ---------------- */
__device__ __forceinline__ u32 tf32c(float f) {
    u32 r;
    asm("cvt.rn.tf32.f32 %0, %1;" : "=r"(r) : "f"(f));
    return r;
}
__device__ __forceinline__ float tanh_hw(float x) {
    float y;
    asm("tanh.approx.f32 %0, %1;" : "=f"(y) : "f"(x));
    return y;
}
__device__ __forceinline__ float sigm(float v) {
    return fmaf(tanh_hw(0.5f * v), 0.5f, 0.5f);
}
__device__ __forceinline__ void ldg4f(float* d, const float* p, bool v) {
    float4 t = make_float4(0.0f, 0.0f, 0.0f, 0.0f);
    if (v) t = *reinterpret_cast<const float4*>(p);
    d[0] = t.x; d[1] = t.y; d[2] = t.z; d[3] = t.w;
}
__device__ __forceinline__ void mma1688(float c[4], const u32 a[4], u32 b0, u32 b1) {
    asm volatile(
        "mma.sync.aligned.m16n8k8.row.col.f32.tf32.tf32.f32 "
        "{%0,%1,%2,%3}, {%4,%5,%6,%7}, {%8,%9}, {%0,%1,%2,%3};"
        : "+f"(c[0]), "+f"(c[1]), "+f"(c[2]), "+f"(c[3])
        : "r"(a[0]), "r"(a[1]), "r"(a[2]), "r"(a[3]), "r"(b0), "r"(b1));
}
__device__ __forceinline__ void mma_pair(float c[4], const u32 ae[4], const u32 ao[4], uint4 B) {
    mma1688(c, ae, B.x, B.y);
    mma1688(c, ao, B.z, B.w);
}
/* rows v0 (gid), v1 (gid+8): 4 contiguous logical k each -> even/odd tile frags */
__device__ __forceinline__ void packA(const float* v0, const float* v1, u32 ae[4], u32 ao[4]) {
    ae[0] = tf32c(v0[0]); ae[1] = tf32c(v1[0]); ae[2] = tf32c(v0[1]); ae[3] = tf32c(v1[1]);
    ao[0] = tf32c(v0[2]); ao[1] = tf32c(v1[2]); ao[2] = tf32c(v0[3]); ao[3] = tf32c(v1[3]);
}

/* ====== prep: one thread per output scalar (max MLP, coalesced stores) ====== */
__global__ void rgcn_prep(const float* __restrict__ wz, const float* __restrict__ wr,
                          const float* __restrict__ wh, const float* __restrict__ wl) {
    int idx = blockIdx.x * blockDim.x + threadIdx.x;
    if (idx >= 38 * 128) return;
    int fid  = idx >> 7;
    int rem  = idx & 127;
    int lane = rem >> 2, j = rem & 3;
    int gid  = lane >> 2, ctg = lane & 3;

    float val;
    u32* dst;
    if (fid < 24) {                 /* B1: z (nt 0..3) | r (nt 4..7) */
        int u = fid >> 3, nt = fid & 7, nt4 = nt & 3;
        int L = ((nt4 >> 1) << 4) + ((nt4 & 1) << 1) + ((gid >> 1) << 2) + (gid & 1);
        int k = u * 16 + ctg * 4 + j;
        val = (nt < 4) ? wz[k * 32 + L] + wz[1536 + k * 32 + L]
                       : wr[k * 32 + L] + wr[1536 + k * 32 + L];
        dst = reinterpret_cast<u32*>(gB1) + (fid * 32 + lane) * 4 + j;
    } else if (fid < 36) {          /* B_h */
        int f = fid - 24;
        int u = f >> 2, nt = f & 3;
        int L = ((nt >> 1) << 4) + ((nt & 1) << 1) + ((gid >> 1) << 2) + (gid & 1);
        int k = u * 16 + ctg * 4 + j;
        val = wh[k * 32 + L] + wh[1536 + k * 32 + L];
        dst = reinterpret_cast<u32*>(gBh) + (f * 32 + lane) * 4 + j;
    } else {                        /* B_lin (identity n) */
        int u = fid - 36;
        int k = u * 16 + ctg * 4 + j;
        val = wl[k * 8 + gid];
        dst = reinterpret_cast<u32*>(gBl) + (u * 32 + lane) * 4 + j;
    }
    *dst = tf32c(val);
}

/* ====== main body: all DRAM loads front-loaded; CHECK templated out ====== */
template <bool CHECK>
__device__ __forceinline__ void rgcn_body(
    const float* __restrict__ x, const float* __restrict__ h,
    const float* __restrict__ bz, const float* __restrict__ br,
    const float* __restrict__ bh, const float* __restrict__ bl,
    float* __restrict__ out, float* __restrict__ hnew, int N, int row0,
    int lane, int c4, int c2)
{
    bool vv[2][2];
    if (CHECK) {
        vv[0][0] = row0 < N;       vv[0][1] = row0 + 8 < N;
        vv[1][0] = row0 + 16 < N;  vv[1][1] = row0 + 24 < N;
    } else {
        vv[0][0] = vv[0][1] = vv[1][0] = vv[1][1] = true;
    }

    const float* xp = x    + (size_t)row0 * IN_DIM + c4;
    const float* hp = h    + (size_t)row0 * HID    + c4;
    float*       np = hnew + (size_t)row0 * HID    + c4;
    float*       op = out  + (size_t)row0 * OUT_DIM + c2;

    /* ---- ALL x and h loads issued up front (max MLP), packed to frags ---- */
    u32 xae[2][4], xao[2][4];        /* pair u=0 */
    u32 hae[2][2][4], hao[2][2][4];  /* [pair u-1][mt] */
    {
        float t0[4], t1[4];
        ldg4f(t0, xp,               vv[0][0]);
        ldg4f(t1, xp +  8 * IN_DIM, vv[0][1]);
        packA(t0, t1, xae[0], xao[0]);
        ldg4f(t0, xp + 16 * IN_DIM, vv[1][0]);
        ldg4f(t1, xp + 24 * IN_DIM, vv[1][1]);
        packA(t0, t1, xae[1], xao[1]);
        #pragma unroll
        for (int p = 0; p < 2; p++)
            #pragma unroll
            for (int mt = 0; mt < 2; mt++) {
                ldg4f(t0, hp + (mt * 16)     * HID + p * 16, vv[mt][0]);
                ldg4f(t1, hp + (mt * 16 + 8) * HID + p * 16, vv[mt][1]);
                packA(t0, t1, hae[p][mt], hao[p][mt]);
            }
    }

    /* ---- GEMM1 (fused z|r): c1 = [x|h] @ B1, operands straight from frags ---- */
    float c1[2][8][4];
    #pragma unroll
    for (int mt = 0; mt < 2; mt++)
        #pragma unroll
        for (int nt = 0; nt < 8; nt++)
            #pragma unroll
            for (int i = 0; i < 4; i++) c1[mt][nt][i] = 0.0f;

    #pragma unroll
    for (int u = 0; u < 3; u++) {
        #pragma unroll
        for (int nt = 0; nt < 8; nt++) {
            uint4 B = __ldg(&gB1[(u * 8 + nt) * 32 + lane]);
            #pragma unroll
            for (int mt = 0; mt < 2; mt++) {
                const u32* ae = (u == 0) ? xae[mt] : hae[u - 1][mt];
                const u32* ao = (u == 0) ? xao[mt] : hao[u - 1][mt];
                mma_pair(c1[mt][nt], ae, ao, B);
            }
        }
    }

    /* ---- epilogue 1: a2 = h_tf32 * sigm(r+br); z-half -> gate in place ----
       h values come from the packed frags (tf32-rounded; re-rounded by GEMM2). */
    u32 a2e[2][2][4], a2o[2][2][4];
    {
        float brA[4], brB[4], bzA[4], bzB[4];
        ldg4f(brA, br + c4, true);
        ldg4f(brB, br + 16 + c4, true);
        ldg4f(bzA, bz + c4, true);
        ldg4f(bzB, bz + 16 + c4, true);
        #pragma unroll
        for (int mt = 0; mt < 2; mt++)
            #pragma unroll
            for (int grp = 0; grp < 2; grp++) {
                const float* brv = grp ? brB : brA;
                const float* bzv = grp ? bzB : bzA;
                float vals[2][4];
                #pragma unroll
                for (int rh = 0; rh < 2; rh++) {
                    #pragma unroll
                    for (int q = 0; q < 4; q++) {
                        int nt = grp * 2 + (q >> 1);
                        int ri = rh * 2 + (q & 1);
                        float hX = __uint_as_float(
                            (q < 2) ? hae[grp][mt][q * 2 + rh]
                                    : hao[grp][mt][(q - 2) * 2 + rh]);
                        vals[rh][q] = hX * sigm(c1[mt][nt + 4][ri] + brv[q]);
                        c1[mt][nt][ri] = sigm(c1[mt][nt][ri] + bzv[q]);
                    }
                }
                packA(vals[0], vals[1], a2e[mt][grp], a2o[mt][grp]);
            }
    }   /* h-frags and c1 r-half dead; z-half holds gates */

    /* ---- GEMM2: cc = [x | a2] @ B_h ---- */
    float cc[2][4][4];
    #pragma unroll
    for (int mt = 0; mt < 2; mt++)
        #pragma unroll
        for (int nt = 0; nt < 4; nt++)
            #pragma unroll
            for (int i = 0; i < 4; i++) cc[mt][nt][i] = 0.0f;

    #pragma unroll
    for (int u = 0; u < 3; u++) {
        #pragma unroll
        for (int nt = 0; nt < 4; nt++) {
            uint4 B = __ldg(&gBh[(u * 4 + nt) * 32 + lane]);
            #pragma unroll
            for (int mt = 0; mt < 2; mt++) {
                const u32* ae = (u == 0) ? xae[mt] : a2e[mt][u - 1];
                const u32* ao = (u == 0) ? xao[mt] : a2o[mt][u - 1];
                mma_pair(cc[mt][nt], ae, ao, B);
            }
        }
    }

    /* ---- epilogue 2: hn = ht + zg*(h - ht); exact h reloaded from L1 ---- */
    u32 re[2][2][4], ro[2][2][4];
    {
        float bhA[4], bhB[4];
        ldg4f(bhA, bh + c4, true);
        ldg4f(bhB, bh + 16 + c4, true);
        #pragma unroll
        for (int mt = 0; mt < 2; mt++)
            #pragma unroll
            for (int grp = 0; grp < 2; grp++) {
                const float* bhv = grp ? bhB : bhA;
                float rel[2][4];
                #pragma unroll
                for (int rh = 0; rh < 2; rh++) {
                    float hX[4];   /* L1-hit reload (exact fp32 h) */
                    ldg4f(hX, hp + (mt * 16 + rh * 8) * HID + grp * 16, vv[mt][rh]);
                    float hn[4];
                    #pragma unroll
                    for (int q = 0; q < 4; q++) {
                        int nt = grp * 2 + (q >> 1);
                        int ri = rh * 2 + (q & 1);
                        float zg = c1[mt][nt][ri];
                        float ht = tanh_hw(cc[mt][nt][ri] + bhv[q]);
                        hn[q] = fmaf(zg, hX[q] - ht, ht);
                        rel[rh][q] = fmaxf(hn[q], 0.0f);
                    }
                    if (vv[mt][rh])
                        *reinterpret_cast<float4*>(np + (mt * 16 + rh * 8) * HID + grp * 16) =
                            make_float4(hn[0], hn[1], hn[2], hn[3]);
                }
                packA(rel[0], rel[1], re[mt][grp], ro[mt][grp]);
            }
    }

    /* ---- GEMM3: out = relu(hn) @ w_lin ---- */
    float co[2][4];
    #pragma unroll
    for (int mt = 0; mt < 2; mt++)
        #pragma unroll
        for (int i = 0; i < 4; i++) co[mt][i] = 0.0f;

    #pragma unroll
    for (int u = 0; u < 2; u++) {
        uint4 B = __ldg(&gBl[u * 32 + lane]);
        #pragma unroll
        for (int mt = 0; mt < 2; mt++)
            mma_pair(co[mt], re[mt][u], ro[mt][u], B);
    }

    float2 blv = *reinterpret_cast<const float2*>(bl + c2);
    #pragma unroll
    for (int mt = 0; mt < 2; mt++) {
        if (vv[mt][0])
            *reinterpret_cast<float2*>(op + (mt * 16) * OUT_DIM) =
                make_float2(co[mt][0] + blv.x, co[mt][1] + blv.y);
        if (vv[mt][1])
            *reinterpret_cast<float2*>(op + (mt * 16 + 8) * OUT_DIM) =
                make_float2(co[mt][2] + blv.x, co[mt][3] + blv.y);
    }
}

__global__ void __launch_bounds__(TPB, 4) rgcn_mma_kernel(
    const float* __restrict__ x, const float* __restrict__ h,
    const float* __restrict__ bz, const float* __restrict__ br,
    const float* __restrict__ bh, const float* __restrict__ bl,
    float* __restrict__ out, float* __restrict__ hnew, int N)
{
    const int tid  = threadIdx.x;
    const int lane = tid & 31;
    const int warp = tid >> 5;
    const int gid  = lane >> 2, ctg = lane & 3;
    const int c4   = 4 * ctg, c2 = 2 * ctg;
    const int row0 = blockIdx.x * TILE_M + warp * 32 + gid;

    if (blockIdx.x + 1 < gridDim.x)
        rgcn_body<false>(x, h, bz, br, bh, bl, out, hnew, N, row0, lane, c4, c2);
    else
        rgcn_body<true>(x, h, bz, br, bh, bl, out, hnew, N, row0, lane, c4, c2);
}

extern "C" void kernel_launch(void* const* d_in, const int* in_sizes, int n_in,
                              void* d_out, int out_size) {
    const float* x  = (const float*)d_in[0];
    const float* h  = (const float*)d_in[3];
    const float* wz = (const float*)d_in[4];
    const float* bz = (const float*)d_in[5];
    const float* wr = (const float*)d_in[6];
    const float* br = (const float*)d_in[7];
    const float* wh = (const float*)d_in[8];
    const float* bh = (const float*)d_in[9];
    const float* wl = (const float*)d_in[10];
    const float* bl = (const float*)d_in[11];

    int N = in_sizes[0] / IN_DIM;
    float* out  = (float*)d_out;
    float* hnew = out + (size_t)N * OUT_DIM;

    rgcn_prep<<<19, 256>>>(wz, wr, wh, wl);

    int grid = (N + TILE_M - 1) / TILE_M;
    rgcn_mma_kernel<<<grid, TPB>>>(x, h, bz, br, bh, bl, out, hnew, N);
}

// round 15
// speedup vs baseline: 1.2617x; 1.2617x over previous
#include <cuda_runtime.h>
#include <cstdint>

typedef uint32_t u32;

#define IN_DIM 16
#define HID 32
#define OUT_DIM 8
#define TPB 128
#define TILE_M 128   /* 4 warps x 32 rows (mt=2) */

/* ---- fragment-ordered tf32 weight tables ----
   uint4 = {b(j=0), b(j=1), b(j=2), b(j=3)} per lane; pairs consumed as (x,y)|(z,w).
   k-perm: pair u, slot j in 0..3  ->  logical k = 16u + 4*ctg + j
   n-perm (32-col groups): slot (nt4, g) -> n = (nt4>>1)*16 + (nt4&1)*2 + (g>>1)*4 + (g&1) */
__device__ uint4 gB1[768];   /* z: nt 0..3 | r: nt 4..7, 3 pairs x 32 lanes */
__device__ uint4 gBh[384];   /* h~ : 3 pairs x 4 nt x 32 lanes */
__device__ uint4 gBl[64];    /* lin: 2 pairs x 1 nt x 32 lanes */

/* ---------------- helpers ---------------- */
__device__ __forceinline__ u32 tf32c(float f) {
    u32 r;
    asm("cvt.rn.tf32.f32 %0, %1;" : "=r"(r) : "f"(f));
    return r;
}
__device__ __forceinline__ float tanh_hw(float x) {
    float y;
    asm("tanh.approx.f32 %0, %1;" : "=f"(y) : "f"(x));
    return y;
}
__device__ __forceinline__ float sigm(float v) {
    return fmaf(tanh_hw(0.5f * v), 0.5f, 0.5f);
}
__device__ __forceinline__ void ldg4f(float* d, const float* p, bool v) {
    float4 t = make_float4(0.0f, 0.0f, 0.0f, 0.0f);
    if (v) t = *reinterpret_cast<const float4*>(p);
    d[0] = t.x; d[1] = t.y; d[2] = t.z; d[3] = t.w;
}
__device__ __forceinline__ void mma1688(float c[4], const u32 a[4], u32 b0, u32 b1) {
    asm volatile(
        "mma.sync.aligned.m16n8k8.row.col.f32.tf32.tf32.f32 "
        "{%0,%1,%2,%3}, {%4,%5,%6,%7}, {%8,%9}, {%0,%1,%2,%3};"
        : "+f"(c[0]), "+f"(c[1]), "+f"(c[2]), "+f"(c[3])
        : "r"(a[0]), "r"(a[1]), "r"(a[2]), "r"(a[3]), "r"(b0), "r"(b1));
}
__device__ __forceinline__ void mma_pair(float c[4], const u32 ae[4], const u32 ao[4], uint4 B) {
    mma1688(c, ae, B.x, B.y);
    mma1688(c, ao, B.z, B.w);
}
/* rows v0 (gid), v1 (gid+8): 4 contiguous logical k each -> even/odd tile frags */
__device__ __forceinline__ void packA(const float* v0, const float* v1, u32 ae[4], u32 ao[4]) {
    ae[0] = tf32c(v0[0]); ae[1] = tf32c(v1[0]); ae[2] = tf32c(v0[1]); ae[3] = tf32c(v1[1]);
    ao[0] = tf32c(v0[2]); ao[1] = tf32c(v1[2]); ao[2] = tf32c(v0[3]); ao[3] = tf32c(v1[3]);
}

/* ====== prep: one thread per output scalar (max MLP, coalesced stores) ====== */
__global__ void rgcn_prep(const float* __restrict__ wz, const float* __restrict__ wr,
                          const float* __restrict__ wh, const float* __restrict__ wl) {
    int idx = blockIdx.x * blockDim.x + threadIdx.x;
    if (idx >= 38 * 128) return;
    int fid  = idx >> 7;
    int rem  = idx & 127;
    int lane = rem >> 2, j = rem & 3;
    int gid  = lane >> 2, ctg = lane & 3;

    float val;
    u32* dst;
    if (fid < 24) {                 /* B1: z (nt 0..3) | r (nt 4..7) */
        int u = fid >> 3, nt = fid & 7, nt4 = nt & 3;
        int L = ((nt4 >> 1) << 4) + ((nt4 & 1) << 1) + ((gid >> 1) << 2) + (gid & 1);
        int k = u * 16 + ctg * 4 + j;
        val = (nt < 4) ? wz[k * 32 + L] + wz[1536 + k * 32 + L]
                       : wr[k * 32 + L] + wr[1536 + k * 32 + L];
        dst = reinterpret_cast<u32*>(gB1) + (fid * 32 + lane) * 4 + j;
    } else if (fid < 36) {          /* B_h */
        int f = fid - 24;
        int u = f >> 2, nt = f & 3;
        int L = ((nt >> 1) << 4) + ((nt & 1) << 1) + ((gid >> 1) << 2) + (gid & 1);
        int k = u * 16 + ctg * 4 + j;
        val = wh[k * 32 + L] + wh[1536 + k * 32 + L];
        dst = reinterpret_cast<u32*>(gBh) + (f * 32 + lane) * 4 + j;
    } else {                        /* B_lin (identity n) */
        int u = fid - 36;
        int k = u * 16 + ctg * 4 + j;
        val = wl[k * 8 + gid];
        dst = reinterpret_cast<u32*>(gBl) + (u * 32 + lane) * 4 + j;
    }
    *dst = tf32c(val);
}

/* ====== main: R13 structure + GEMM2 x-part hoisted for phase overlap ====== */
__global__ void __launch_bounds__(TPB, 4) rgcn_mma_kernel(
    const float* __restrict__ x, const float* __restrict__ h,
    const float* __restrict__ bz, const float* __restrict__ br,
    const float* __restrict__ bh, const float* __restrict__ bl,
    float* __restrict__ out, float* __restrict__ hnew, int N)
{
    const int tid  = threadIdx.x;
    const int lane = tid & 31;
    const int warp = tid >> 5;
    const int gid  = lane >> 2, ctg = lane & 3;
    const int c4   = 4 * ctg, c2 = 2 * ctg;
    const int row0 = blockIdx.x * TILE_M + warp * 32 + gid;

    bool vv[2][2];
    vv[0][0] = row0 < N;       vv[0][1] = row0 + 8 < N;
    vv[1][0] = row0 + 16 < N;  vv[1][1] = row0 + 24 < N;

    const float* xp = x    + (size_t)row0 * IN_DIM + c4;
    const float* hp = h    + (size_t)row0 * HID    + c4;
    float*       np = hnew + (size_t)row0 * HID    + c4;
    float*       op = out  + (size_t)row0 * OUT_DIM + c2;

    /* ---- x loaded once, kept only as tf32 fragments ---- */
    u32 xae[2][4], xao[2][4];
    {
        float t0[4], t1[4];
        ldg4f(t0, xp,               vv[0][0]);
        ldg4f(t1, xp +  8 * IN_DIM, vv[0][1]);
        packA(t0, t1, xae[0], xao[0]);
        ldg4f(t0, xp + 16 * IN_DIM, vv[1][0]);
        ldg4f(t1, xp + 24 * IN_DIM, vv[1][1]);
        packA(t0, t1, xae[1], xao[1]);
    }

    /* ---- GEMM1 (fused z|r): c1 = [x|h] @ B1; h packed transiently per pair ---- */
    float c1[2][8][4];
    #pragma unroll
    for (int mt = 0; mt < 2; mt++)
        #pragma unroll
        for (int nt = 0; nt < 8; nt++)
            #pragma unroll
            for (int i = 0; i < 4; i++) c1[mt][nt][i] = 0.0f;

    #pragma unroll
    for (int u = 0; u < 3; u++) {
        u32 ae[2][4], ao[2][4];
        if (u == 0) {
            #pragma unroll
            for (int mt = 0; mt < 2; mt++)
                #pragma unroll
                for (int j = 0; j < 4; j++) { ae[mt][j] = xae[mt][j]; ao[mt][j] = xao[mt][j]; }
        } else {
            const int off = (u - 1) * 16;
            float t0[4], t1[4];
            ldg4f(t0, hp + off,            vv[0][0]);
            ldg4f(t1, hp + 8 * HID + off,  vv[0][1]);
            packA(t0, t1, ae[0], ao[0]);
            ldg4f(t0, hp + 16 * HID + off, vv[1][0]);
            ldg4f(t1, hp + 24 * HID + off, vv[1][1]);
            packA(t0, t1, ae[1], ao[1]);
        }
        #pragma unroll
        for (int nt = 0; nt < 8; nt++) {
            uint4 B = __ldg(&gB1[(u * 8 + nt) * 32 + lane]);
            mma_pair(c1[0][nt], ae[0], ao[0], B);
            mma_pair(c1[1][nt], ae[1], ao[1], B);
        }
    }

    /* ---- OVERLAP: GEMM2's x-contribution (independent of c1) fills the
           tensor pipe while GEMM1's accumulators drain ---- */
    float cc[2][4][4];
    #pragma unroll
    for (int mt = 0; mt < 2; mt++)
        #pragma unroll
        for (int nt = 0; nt < 4; nt++)
            #pragma unroll
            for (int i = 0; i < 4; i++) cc[mt][nt][i] = 0.0f;

    #pragma unroll
    for (int nt = 0; nt < 4; nt++) {
        uint4 B = __ldg(&gBh[nt * 32 + lane]);   /* u = 0 */
        mma_pair(cc[0][nt], xae[0], xao[0], B);
        mma_pair(cc[1][nt], xae[1], xao[1], B);
    }

    /* ---- epilogue 1: a2 = h * sigm(r+br) (h reloaded from L1);
           z-half of c1 converted to gate in place ---- */
    u32 a2e[2][2][4], a2o[2][2][4];
    {
        float brA[4], brB[4], bzA[4], bzB[4];
        ldg4f(brA, br + c4, true);
        ldg4f(brB, br + 16 + c4, true);
        ldg4f(bzA, bz + c4, true);
        ldg4f(bzB, bz + 16 + c4, true);
        #pragma unroll
        for (int mt = 0; mt < 2; mt++)
            #pragma unroll
            for (int grp = 0; grp < 2; grp++) {
                const float* brv = grp ? brB : brA;
                const float* bzv = grp ? bzB : bzA;
                float vals[2][4];
                #pragma unroll
                for (int rh = 0; rh < 2; rh++) {
                    float hX[4];   /* L1-hit reload */
                    ldg4f(hX, hp + (mt * 16 + rh * 8) * HID + grp * 16, vv[mt][rh]);
                    #pragma unroll
                    for (int q = 0; q < 4; q++) {
                        int nt = grp * 2 + (q >> 1);
                        int ri = rh * 2 + (q & 1);
                        vals[rh][q] = hX[q] * sigm(c1[mt][nt + 4][ri] + brv[q]);
                        c1[mt][nt][ri] = sigm(c1[mt][nt][ri] + bzv[q]);
                    }
                }
                packA(vals[0], vals[1], a2e[mt][grp], a2o[mt][grp]);
            }
    }   /* r-half of c1 dead; z-half now holds gates */

    /* ---- GEMM2 remainder: u = 1, 2 (a2 contribution) ---- */
    #pragma unroll
    for (int u = 1; u < 3; u++) {
        #pragma unroll
        for (int nt = 0; nt < 4; nt++) {
            uint4 B = __ldg(&gBh[(u * 4 + nt) * 32 + lane]);
            #pragma unroll
            for (int mt = 0; mt < 2; mt++)
                mma_pair(cc[mt][nt], a2e[mt][u - 1], a2o[mt][u - 1], B);
        }
    }   /* a2 dead after here */

    /* ---- epilogue 2: hn = ht + zg*(h - ht); store; pack relu(hn) ---- */
    u32 re[2][2][4], ro[2][2][4];
    {
        float bhA[4], bhB[4];
        ldg4f(bhA, bh + c4, true);
        ldg4f(bhB, bh + 16 + c4, true);
        #pragma unroll
        for (int mt = 0; mt < 2; mt++)
            #pragma unroll
            for (int grp = 0; grp < 2; grp++) {
                const float* bhv = grp ? bhB : bhA;
                float rel[2][4];
                #pragma unroll
                for (int rh = 0; rh < 2; rh++) {
                    float hX[4];   /* L1-hit reload */
                    ldg4f(hX, hp + (mt * 16 + rh * 8) * HID + grp * 16, vv[mt][rh]);
                    float hn[4];
                    #pragma unroll
                    for (int q = 0; q < 4; q++) {
                        int nt = grp * 2 + (q >> 1);
                        int ri = rh * 2 + (q & 1);
                        float zg = c1[mt][nt][ri];
                        float ht = tanh_hw(cc[mt][nt][ri] + bhv[q]);
                        hn[q] = fmaf(zg, hX[q] - ht, ht);
                        rel[rh][q] = fmaxf(hn[q], 0.0f);
                    }
                    if (vv[mt][rh])
                        *reinterpret_cast<float4*>(np + (mt * 16 + rh * 8) * HID + grp * 16) =
                            make_float4(hn[0], hn[1], hn[2], hn[3]);
                }
                packA(rel[0], rel[1], re[mt][grp], ro[mt][grp]);
            }
    }

    /* ---- GEMM3: out[32x8] = relu(hn) @ w_lin ---- */
    float co[2][4];
    #pragma unroll
    for (int mt = 0; mt < 2; mt++)
        #pragma unroll
        for (int i = 0; i < 4; i++) co[mt][i] = 0.0f;

    #pragma unroll
    for (int u = 0; u < 2; u++) {
        uint4 B = __ldg(&gBl[u * 32 + lane]);
        #pragma unroll
        for (int mt = 0; mt < 2; mt++)
            mma_pair(co[mt], re[mt][u], ro[mt][u], B);
    }

    float2 blv = *reinterpret_cast<const float2*>(bl + c2);
    #pragma unroll
    for (int mt = 0; mt < 2; mt++) {
        if (vv[mt][0])
            *reinterpret_cast<float2*>(op + (mt * 16) * OUT_DIM) =
                make_float2(co[mt][0] + blv.x, co[mt][1] + blv.y);
        if (vv[mt][1])
            *reinterpret_cast<float2*>(op + (mt * 16 + 8) * OUT_DIM) =
                make_float2(co[mt][2] + blv.x, co[mt][3] + blv.y);
    }
}

extern "C" void kernel_launch(void* const* d_in, const int* in_sizes, int n_in,
                              void* d_out, int out_size) {
    const float* x  = (const float*)d_in[0];
    const float* h  = (const float*)d_in[3];
    const float* wz = (const float*)d_in[4];
    const float* bz = (const float*)d_in[5];
    const float* wr = (const float*)d_in[6];
    const float* br = (const float*)d_in[7];
    const float* wh = (const float*)d_in[8];
    const float* bh = (const float*)d_in[9];
    const float* wl = (const float*)d_in[10];
    const float* bl = (const float*)d_in[11];

    int N = in_sizes[0] / IN_DIM;
    float* out  = (float*)d_out;
    float* hnew = out + (size_t)N * OUT_DIM;

    rgcn_prep<<<19, 256>>>(wz, wr, wh, wl);

    int grid = (N + TILE_M - 1) / TILE_M;
    rgcn_mma_kernel<<<grid, TPB>>>(x, h, bz, br, bh, bl, out, hnew, N);
}